// round 12
// baseline (speedup 1.0000x reference)
#include <cuda_runtime.h>
#include <cstdint>

// ---------------- problem constants ----------------
#define W_IMG 512
#define H_IMG 512
#define CCH   3
#define BATCH 32
#define KSZ   32
#define PAD_LO 15            // SAME padding, even kernel: lo=15, hi=16
#define XPAD  544            // 15 + 512 + 17 (halo baked into packed image)

#define NTH   128            // 4 warps
#define MSEG  128            // rows per segment; CTA covers 2 segments = 256 rows
#define YH    2              // 512 / 256
#define NBLOCKS (YH * W_IMG * CCH)            // 3072
#define N_PRED ((size_t)BATCH * W_IMG * H_IMG * CCH)

// smem union (u32 units):
//   staging buf p: raw[288] tf32 @ RAW_OFF(p)  (256 rows + 31 halo, padded),
//                  B tf32 n-major [32 b rows x pitch 36] @ B_OFF(p)
//   epilogue:      s_d [32 n x pitch 132] floats, reuses same storage
#define RAWLEN 288
#define BPITCH 36            // pitch ≡ 4 (mod 32): conflict-free frag loads
#define BUFLEN (RAWLEN + BATCH * BPITCH)   // 1440
#define RAW_OFF(p) ((p) * BUFLEN)
#define B_OFF(p)   ((p) * BUFLEN + RAWLEN)
#define DPITCH 132
#define SMEM_U32 (BATCH * DPITCH)          // 4224 >= 2*BUFLEN (2880)

__device__ double       g_partials[NBLOCKS];
__device__ unsigned int g_done = 0;
// packed, tf32-converted, zero-padded scratch (static device arrays: legal)
__device__ __align__(16) uint32_t g_img_packed[CCH * XPAD * XPAD];          // 3.55 MB
__device__ __align__(16) uint32_t g_psf_packed[CCH * KSZ * BATCH * KSZ];    // 393 KB

static __device__ __forceinline__ uint32_t f2tf(float v) {
    uint32_t r;
    asm("cvt.rna.tf32.f32 %0, %1;" : "=r"(r) : "f"(v));
    return r;
}
static __device__ __forceinline__ uint32_t smem_u32(const void* p) {
    uint32_t a;
    asm("{ .reg .u64 t; cvta.to.shared.u64 t, %1; cvt.u32.u64 %0, t; }"
        : "=r"(a) : "l"(p));
    return a;
}
static __device__ __forceinline__ void cp_async16(uint32_t dst, const void* src) {
    asm volatile("cp.async.cg.shared.global [%0], [%1], 16;"
                 :: "r"(dst), "l"(src) : "memory");
}

// D(16x8,f32) += A(16x8,tf32,row) * B(8x8,tf32,col)
static __device__ __forceinline__ void mma_tf32(float* d,
                                                uint32_t a0, uint32_t a1,
                                                uint32_t a2, uint32_t a3,
                                                uint32_t b0, uint32_t b1) {
    asm volatile(
        "mma.sync.aligned.m16n8k8.row.col.f32.tf32.tf32.f32 "
        "{%0,%1,%2,%3}, {%4,%5,%6,%7}, {%8,%9}, {%0,%1,%2,%3};"
        : "+f"(d[0]), "+f"(d[1]), "+f"(d[2]), "+f"(d[3])
        : "r"(a0), "r"(a1), "r"(a2), "r"(a3), "r"(b0), "r"(b1));
}

// ---------------- pack pre-pass ----------------
__global__ void pack_kernel(const float* __restrict__ img,
                            const float* __restrict__ psf) {
    const int stride = gridDim.x * blockDim.x;
    const int n_img = CCH * XPAD * XPAD;
    for (int i = blockIdx.x * blockDim.x + threadIdx.x; i < n_img; i += stride) {
        int c   = i / (XPAD * XPAD);
        int rem = i - c * XPAD * XPAD;
        int X = rem / XPAD, Y = rem - (rem / XPAD) * XPAD;
        int gx = X - PAD_LO, gy = Y - PAD_LO;
        uint32_t v = 0u;
        if ((unsigned)gx < W_IMG && (unsigned)gy < H_IMG)
            v = f2tf(img[((size_t)gx * H_IMG + gy) * CCH + c]);
        g_img_packed[i] = v;
    }
    const int n_psf = CCH * KSZ * BATCH * KSZ;
    for (int i = blockIdx.x * blockDim.x + threadIdx.x; i < n_psf; i += stride) {
        int c    = i / (KSZ * BATCH * KSZ);
        int rem  = i - c * (KSZ * BATCH * KSZ);
        int r    = rem / (BATCH * KSZ);
        int rem2 = rem - r * (BATCH * KSZ);
        int b = rem2 >> 5, s = rem2 & 31;
        g_psf_packed[i] = f2tf(psf[((size_t)(b * KSZ + r) * KSZ + s) * CCH + c]);
    }
}

// ---------------- main kernel ----------------
__global__ __launch_bounds__(NTH, 2)
void conv_mma_kernel(const float* __restrict__ obs,
                     float* __restrict__ out,
                     long long loss_idx)
{
    __shared__ __align__(16) uint32_t s_u[SMEM_U32];
    __shared__ float  s_red[NTH / 32];
    __shared__ double s_dred[NTH / 32];
    __shared__ int    s_last;

    const int tid   = threadIdx.x;
    const int wid   = tid >> 5;
    const int lane  = tid & 31;
    const int yh    = blockIdx.x;        // which 256-row half
    const int x     = blockIdx.y;
    const int c     = blockIdx.z;
    const int ybase = yh * (2 * MSEG);

    const int g  = lane >> 2;            // fragment row
    const int t4 = lane & 3;             // fragment col/k

    // accumulators: [seg][mt][nt][4]; warp w owns rows 32w..32w+31 of each segment
    float d[2][2][4][4];
#pragma unroll
    for (int sg = 0; sg < 2; ++sg)
#pragma unroll
        for (int mt = 0; mt < 2; ++mt)
#pragma unroll
            for (int nt = 0; nt < 4; ++nt)
#pragma unroll
                for (int i = 0; i < 4; ++i) d[sg][mt][nt][i] = 0.f;

    const uint32_t su = smem_u32(s_u);

    // async stage of PSF row r into buffer p (tf32 bits, halo pre-baked)
    auto stage_async = [&](int r, int p) {
        const uint32_t* src_raw =
            g_img_packed + ((size_t)(c * XPAD + (x + r))) * XPAD + ybase;
        if (tid < RAWLEN / 4)
            cp_async16(su + (uint32_t)(RAW_OFF(p) + tid * 4) * 4,
                       src_raw + tid * 4);
        const uint32_t* src_b =
            g_psf_packed + ((size_t)(c * KSZ + r) * BATCH) * KSZ;
#pragma unroll
        for (int j = 0; j < 2; ++j) {
            int e = tid + j * NTH;          // 16B-chunk id: b = e/8, s4 = e%8
            int b = e >> 3, s4 = e & 7;
            cp_async16(su + (uint32_t)(B_OFF(p) + b * BPITCH + s4 * 4) * 4,
                       src_b + b * KSZ + s4 * 4);
        }
        asm volatile("cp.async.commit_group;" ::: "memory");
    };

    stage_async(0, 0);
    asm volatile("cp.async.wait_group 0;" ::: "memory");
    __syncthreads();

    const int abase = 32 * wid + g + t4;

#pragma unroll 1
    for (int r = 0; r < KSZ; ++r) {
        if (r + 1 < KSZ) stage_async(r + 1, (r + 1) & 1);

        const uint32_t* raw = s_u + RAW_OFF(r & 1);
        const uint32_t* Bs  = s_u + B_OFF(r & 1);

        // Toeplitz A register cache: 14 distinct words per segment
        uint32_t rv[2][14];
#pragma unroll
        for (int t = 0; t < 14; ++t) {
            rv[0][t] = raw[abase + 4 * t];
            rv[1][t] = raw[abase + 4 * t + MSEG];
        }

#pragma unroll
        for (int k8 = 0; k8 < 4; ++k8) {
            uint32_t b0[4], b1[4];
#pragma unroll
            for (int nt = 0; nt < 4; ++nt) {
                const int off = (nt * 8 + g) * BPITCH + k8 * 8 + t4;
                b0[nt] = Bs[off];
                b1[nt] = Bs[off + 4];
            }
#pragma unroll
            for (int sg = 0; sg < 2; ++sg)
#pragma unroll
                for (int mt = 0; mt < 2; ++mt) {
                    const int t0 = 4 * mt + 2 * k8;
                    const uint32_t a0 = rv[sg][t0];
                    const uint32_t a1 = rv[sg][t0 + 2];
                    const uint32_t a2 = rv[sg][t0 + 1];
                    const uint32_t a3 = rv[sg][t0 + 3];
#pragma unroll
                    for (int nt = 0; nt < 4; ++nt)
                        mma_tf32(d[sg][mt][nt], a0, a1, a2, a3, b0[nt], b1[nt]);
                }
        }

        asm volatile("cp.async.wait_group 0;" ::: "memory");
        __syncthreads();
    }

    // ---------------- epilogue: per segment, transpose -> gmem + loss ----------------
    float lsum = 0.f;
#pragma unroll 1
    for (int sg = 0; sg < 2; ++sg) {
#pragma unroll
        for (int mt = 0; mt < 2; ++mt)
#pragma unroll
            for (int nt = 0; nt < 4; ++nt)
#pragma unroll
                for (int i = 0; i < 4; ++i) {
                    const int n = nt * 8 + 2 * t4 + (i & 1);
                    const int y = 32 * wid + 16 * mt + g + ((i >> 1) ? 8 : 0);
                    s_u[n * DPITCH + y] = __float_as_uint(d[sg][mt][nt][i]);
                }
        __syncthreads();

        const int bb = tid >> 2;
        const int yq = tid & 3;
        const uint32_t* drow = s_u + bb * DPITCH + yq * 32;
        const int y0 = ybase + sg * MSEG + yq * 32;
        const size_t obase =
            ((size_t)((size_t)bb * W_IMG + x) * H_IMG + y0) * CCH + c;
#pragma unroll
        for (int i = 0; i < 32; ++i) {
            float p = __uint_as_float(drow[i]);
            size_t idx = obase + (size_t)i * CCH;
            out[idx] = p;
            float dd = obs[idx] - p;
            lsum += dd * dd;
        }
        __syncthreads();
    }

    // block reduce loss
#pragma unroll
    for (int off = 16; off; off >>= 1)
        lsum += __shfl_xor_sync(0xffffffffu, lsum, off);
    if (lane == 0) s_red[wid] = lsum;
    __syncthreads();

    const int lin = yh + YH * (x + W_IMG * c);
    if (tid == 0) {
        float bsum = 0.f;
#pragma unroll
        for (int w = 0; w < NTH / 32; ++w) bsum += s_red[w];
        g_partials[lin] = (double)bsum;
        __threadfence();
        unsigned prev = atomicAdd(&g_done, 1u);
        s_last = (prev == NBLOCKS - 1);
    }
    __syncthreads();

    if (s_last) {
        double dsum = 0.0;
        for (int i = tid; i < NBLOCKS; i += NTH) dsum += g_partials[i];
#pragma unroll
        for (int off = 16; off; off >>= 1)
            dsum += __shfl_xor_sync(0xffffffffu, dsum, off);
        if (lane == 0) s_dred[wid] = dsum;
        __syncthreads();
        if (tid == 0) {
            double tot = 0.0;
#pragma unroll
            for (int w = 0; w < NTH / 32; ++w) tot += s_dred[w];
            out[loss_idx] = (float)(tot / (double)N_PRED);
            g_done = 0;   // self-reset: deterministic across graph replays
        }
    }
}

extern "C" void kernel_launch(void* const* d_in, const int* in_sizes, int n_in,
                              void* d_out, int out_size) {
    const float* obs = nullptr;
    const float* img = nullptr;
    const float* psf = nullptr;
    for (int i = 0; i < n_in; ++i) {
        long long n = in_sizes[i];
        if (n == (long long)BATCH * W_IMG * H_IMG * CCH)      obs = (const float*)d_in[i];
        else if (n == (long long)W_IMG * H_IMG * CCH)         img = (const float*)d_in[i];
        else if (n == (long long)BATCH * KSZ * KSZ * CCH)     psf = (const float*)d_in[i];
    }
    float* out = (float*)d_out;

    pack_kernel<<<1024, 256>>>(img, psf);
    dim3 grid(YH, W_IMG, CCH);   // 3072 CTAs
    conv_mma_kernel<<<grid, NTH>>>(obs, out, (long long)out_size - 1);
}

// round 13
// speedup vs baseline: 1.0072x; 1.0072x over previous
#include <cuda_runtime.h>
#include <cstdint>

// ---------------- problem constants ----------------
#define W_IMG 512
#define H_IMG 512
#define CCH   3
#define BATCH 32
#define KSZ   32
#define PAD_LO 15            // SAME padding, even kernel: lo=15, hi=16
#define XPAD  544            // 15 + 512 + 17 (halo baked into packed image)

#define MTILE 128            // y-pixels per CTA (GEMM M)
#define NTH   128            // 4 warps
#define YTILES (H_IMG / MTILE)                // 4
#define NBLOCKS (YTILES * W_IMG * CCH)        // 6144
#define N_PRED ((size_t)BATCH * W_IMG * H_IMG * CCH)

// smem union (u32 units):
//   staging buf p: raw[160] tf32 @ RAW_OFF(p),
//                  B tf32 n-major [32 b rows x pitch 36] @ B_OFF(p)
//   epilogue:      s_d [32 n x pitch 132] floats, reuses same storage
#define RAWLEN 160
#define BPITCH 36            // pitch ≡ 4 (mod 32): conflict-free frag loads
#define BUFLEN (RAWLEN + BATCH * BPITCH)   // 1312
#define RAW_OFF(p) ((p) * BUFLEN)
#define B_OFF(p)   ((p) * BUFLEN + RAWLEN)
#define DPITCH 132
#define SMEM_U32 (BATCH * DPITCH)          // 4224 >= 2*BUFLEN (2624)

__device__ double       g_partials[NBLOCKS];
__device__ unsigned int g_done = 0;
// packed, tf32-converted, zero-padded scratch (static device arrays: legal)
__device__ __align__(16) uint32_t g_img_packed[CCH * XPAD * XPAD];          // 3.55 MB
__device__ __align__(16) uint32_t g_psf_packed[CCH * KSZ * BATCH * KSZ];    // 393 KB

static __device__ __forceinline__ uint32_t f2tf(float v) {
    uint32_t r;
    asm("cvt.rna.tf32.f32 %0, %1;" : "=r"(r) : "f"(v));
    return r;
}
static __device__ __forceinline__ uint32_t smem_u32(const void* p) {
    uint32_t a;
    asm("{ .reg .u64 t; cvta.to.shared.u64 t, %1; cvt.u32.u64 %0, t; }"
        : "=r"(a) : "l"(p));
    return a;
}
static __device__ __forceinline__ void cp_async16(uint32_t dst, const void* src) {
    asm volatile("cp.async.cg.shared.global [%0], [%1], 16;"
                 :: "r"(dst), "l"(src) : "memory");
}

// D(16x8,f32) += A(16x8,tf32,row) * B(8x8,tf32,col)
static __device__ __forceinline__ void mma_tf32(float* d,
                                                uint32_t a0, uint32_t a1,
                                                uint32_t a2, uint32_t a3,
                                                uint32_t b0, uint32_t b1) {
    asm volatile(
        "mma.sync.aligned.m16n8k8.row.col.f32.tf32.tf32.f32 "
        "{%0,%1,%2,%3}, {%4,%5,%6,%7}, {%8,%9}, {%0,%1,%2,%3};"
        : "+f"(d[0]), "+f"(d[1]), "+f"(d[2]), "+f"(d[3])
        : "r"(a0), "r"(a1), "r"(a2), "r"(a3), "r"(b0), "r"(b1));
}

// ---------------- pack pre-pass ----------------
__global__ void pack_kernel(const float* __restrict__ img,
                            const float* __restrict__ psf) {
    const int stride = gridDim.x * blockDim.x;
    const int n_img = CCH * XPAD * XPAD;
    for (int i = blockIdx.x * blockDim.x + threadIdx.x; i < n_img; i += stride) {
        int c   = i / (XPAD * XPAD);
        int rem = i - c * XPAD * XPAD;
        int X = rem / XPAD, Y = rem - (rem / XPAD) * XPAD;
        int gx = X - PAD_LO, gy = Y - PAD_LO;
        uint32_t v = 0u;
        if ((unsigned)gx < W_IMG && (unsigned)gy < H_IMG)
            v = f2tf(img[((size_t)gx * H_IMG + gy) * CCH + c]);
        g_img_packed[i] = v;
    }
    const int n_psf = CCH * KSZ * BATCH * KSZ;
    for (int i = blockIdx.x * blockDim.x + threadIdx.x; i < n_psf; i += stride) {
        int c    = i / (KSZ * BATCH * KSZ);
        int rem  = i - c * (KSZ * BATCH * KSZ);
        int r    = rem / (BATCH * KSZ);
        int rem2 = rem - r * (BATCH * KSZ);
        int b = rem2 >> 5, s = rem2 & 31;
        g_psf_packed[i] = f2tf(psf[((size_t)(b * KSZ + r) * KSZ + s) * CCH + c]);
    }
}

// ---------------- main kernel ----------------
__global__ __launch_bounds__(NTH, 5)
void conv_mma_kernel(const float* __restrict__ obs,
                     float* __restrict__ out,
                     long long loss_idx)
{
    __shared__ __align__(16) uint32_t s_u[SMEM_U32];
    __shared__ float  s_red[NTH / 32];
    __shared__ double s_dred[NTH / 32];
    __shared__ int    s_last;

    const int tid   = threadIdx.x;
    const int wid   = tid >> 5;
    const int lane  = tid & 31;
    const int ytile = blockIdx.x;
    const int x     = blockIdx.y;
    const int c     = blockIdx.z;
    const int y0    = ytile * MTILE;

    const int g  = lane >> 2;        // fragment row
    const int t4 = lane & 3;         // fragment col/k

    float d[2][4][4];
#pragma unroll
    for (int mt = 0; mt < 2; ++mt)
#pragma unroll
        for (int nt = 0; nt < 4; ++nt)
#pragma unroll
            for (int i = 0; i < 4; ++i) d[mt][nt][i] = 0.f;

    const uint32_t su = smem_u32(s_u);

    // async stage of PSF row r into buffer p (tf32 bits, halo pre-baked)
    auto stage_async = [&](int r, int p) {
        const uint32_t* src_raw =
            g_img_packed + ((size_t)(c * XPAD + (x + r))) * XPAD + y0;
        if (tid < RAWLEN / 4)
            cp_async16(su + (uint32_t)(RAW_OFF(p) + tid * 4) * 4,
                       src_raw + tid * 4);
        const uint32_t* src_b =
            g_psf_packed + ((size_t)(c * KSZ + r) * BATCH) * KSZ;
#pragma unroll
        for (int j = 0; j < 2; ++j) {
            int e = tid + j * NTH;          // 16B-chunk id: b = e/8, s4 = e%8
            int b = e >> 3, s4 = e & 7;
            cp_async16(su + (uint32_t)(B_OFF(p) + b * BPITCH + s4 * 4) * 4,
                       src_b + b * KSZ + s4 * 4);
        }
        asm volatile("cp.async.commit_group;" ::: "memory");
    };

    stage_async(0, 0);
    asm volatile("cp.async.wait_group 0;" ::: "memory");
    __syncthreads();

    const int abase = 32 * wid + g + t4;
    const int bfrag = g * BPITCH + t4;   // base of B fragment addressing

#pragma unroll 1
    for (int r = 0; r < KSZ; ++r) {
        if (r + 1 < KSZ) stage_async(r + 1, (r + 1) & 1);

        const uint32_t* raw = s_u + RAW_OFF(r & 1);
        const uint32_t* Bs  = s_u + B_OFF(r & 1);

        // Toeplitz A register cache: 14 distinct words cover all fragments
        uint32_t rv[14];
#pragma unroll
        for (int t = 0; t < 14; ++t) rv[t] = raw[abase + 4 * t];

        // -------- B-fragment double buffer across k8 --------
        uint32_t bA0[4], bA1[4], bB0[4], bB1[4];
#pragma unroll
        for (int nt = 0; nt < 4; ++nt) {              // preload k8 = 0
            const int off = bfrag + nt * 8 * BPITCH;  // (k=t4, n=nt*8+g)
            bA0[nt] = Bs[off];
            bA1[nt] = Bs[off + 4];
        }

#pragma unroll
        for (int k8 = 0; k8 < 4; ++k8) {
            uint32_t* c0 = (k8 & 1) ? bB0 : bA0;
            uint32_t* c1 = (k8 & 1) ? bB1 : bA1;
            uint32_t* n0 = (k8 & 1) ? bA0 : bB0;
            uint32_t* n1 = (k8 & 1) ? bA1 : bB1;
            if (k8 < 3) {                              // issue next-k8 LDS first
#pragma unroll
                for (int nt = 0; nt < 4; ++nt) {
                    const int off = bfrag + nt * 8 * BPITCH + (k8 + 1) * 8;
                    n0[nt] = Bs[off];
                    n1[nt] = Bs[off + 4];
                }
            }
#pragma unroll
            for (int mt = 0; mt < 2; ++mt) {           // MMA burst on current
                const int t0 = 4 * mt + 2 * k8;
                const uint32_t a0 = rv[t0];
                const uint32_t a1 = rv[t0 + 2];
                const uint32_t a2 = rv[t0 + 1];
                const uint32_t a3 = rv[t0 + 3];
#pragma unroll
                for (int nt = 0; nt < 4; ++nt)
                    mma_tf32(d[mt][nt], a0, a1, a2, a3, c0[nt], c1[nt]);
            }
        }

        asm volatile("cp.async.wait_group 0;" ::: "memory");
        __syncthreads();
    }

    // ---------------- epilogue: D -> smem transpose -> gmem + loss ----------------
#pragma unroll
    for (int mt = 0; mt < 2; ++mt)
#pragma unroll
        for (int nt = 0; nt < 4; ++nt)
#pragma unroll
            for (int i = 0; i < 4; ++i) {
                const int n = nt * 8 + 2 * t4 + (i & 1);
                const int y = 32 * wid + 16 * mt + g + ((i >> 1) ? 8 : 0);
                s_u[n * DPITCH + y] = __float_as_uint(d[mt][nt][i]);
            }
    __syncthreads();

    const int bb = tid >> 2;
    const int yq = tid & 3;
    const uint32_t* drow = s_u + bb * DPITCH + yq * 32;
    const size_t obase =
        ((size_t)((size_t)bb * W_IMG + x) * H_IMG + (y0 + yq * 32)) * CCH + c;
    float lsum = 0.f;
#pragma unroll
    for (int i = 0; i < 32; ++i) {
        float p = __uint_as_float(drow[i]);
        size_t idx = obase + (size_t)i * CCH;
        out[idx] = p;
        float dd = obs[idx] - p;
        lsum += dd * dd;
    }

#pragma unroll
    for (int off = 16; off; off >>= 1)
        lsum += __shfl_xor_sync(0xffffffffu, lsum, off);
    if (lane == 0) s_red[wid] = lsum;
    __syncthreads();

    const int lin = ytile + YTILES * (x + W_IMG * c);
    if (tid == 0) {
        float bsum = 0.f;
#pragma unroll
        for (int w = 0; w < NTH / 32; ++w) bsum += s_red[w];
        g_partials[lin] = (double)bsum;
        __threadfence();
        unsigned prev = atomicAdd(&g_done, 1u);
        s_last = (prev == NBLOCKS - 1);
    }
    __syncthreads();

    if (s_last) {
        double dsum = 0.0;
        for (int i = tid; i < NBLOCKS; i += NTH) dsum += g_partials[i];
#pragma unroll
        for (int off = 16; off; off >>= 1)
            dsum += __shfl_xor_sync(0xffffffffu, dsum, off);
        if (lane == 0) s_dred[wid] = dsum;
        __syncthreads();
        if (tid == 0) {
            double tot = 0.0;
#pragma unroll
            for (int w = 0; w < NTH / 32; ++w) tot += s_dred[w];
            out[loss_idx] = (float)(tot / (double)N_PRED);
            g_done = 0;   // self-reset: deterministic across graph replays
        }
    }
}

extern "C" void kernel_launch(void* const* d_in, const int* in_sizes, int n_in,
                              void* d_out, int out_size) {
    const float* obs = nullptr;
    const float* img = nullptr;
    const float* psf = nullptr;
    for (int i = 0; i < n_in; ++i) {
        long long n = in_sizes[i];
        if (n == (long long)BATCH * W_IMG * H_IMG * CCH)      obs = (const float*)d_in[i];
        else if (n == (long long)W_IMG * H_IMG * CCH)         img = (const float*)d_in[i];
        else if (n == (long long)BATCH * KSZ * KSZ * CCH)     psf = (const float*)d_in[i];
    }
    float* out = (float*)d_out;

    pack_kernel<<<1024, 256>>>(img, psf);
    dim3 grid(YTILES, W_IMG, CCH);   // 6144 CTAs
    conv_mma_kernel<<<grid, NTH>>>(obs, out, (long long)out_size - 1);
}

// round 15
// speedup vs baseline: 1.3355x; 1.3259x over previous
#include <cuda_runtime.h>
#include <cstdint>

// ---------------- problem constants ----------------
#define W_IMG 512
#define H_IMG 512
#define CCH   3
#define BATCH 32
#define KSZ   32
#define PAD_LO 15            // SAME padding, even kernel: lo=15, hi=16
#define XPAD  544            // 15 + 512 + 17 (halo baked into packed image)

#define NTH   256            // 8 warps: two 4-warp groups, one per 128-row segment
#define MSEG  128
#define MCTA  256            // rows per CTA
#define YH    (H_IMG / MCTA)                  // 2
#define NBLOCKS (YH * W_IMG * CCH)            // 3072
#define N_PRED ((size_t)BATCH * W_IMG * H_IMG * CCH)

// smem union (u32 units):
//   staging buf p: raw[288] tf32 @ RAW_OFF(p)  (256 rows + 31 halo + pad),
//                  B tf32 n-major [32 b rows x pitch 36] @ B_OFF(p)
//   epilogue:      s_d [32 n x pitch 260] floats
#define RAWLEN 288
#define BPITCH 36            // pitch ≡ 4 (mod 32): conflict-free frag loads
#define BUFLEN (RAWLEN + BATCH * BPITCH)   // 1440
#define RAW_OFF(p) ((p) * BUFLEN)
#define B_OFF(p)   ((p) * BUFLEN + RAWLEN)
#define DPITCH 260
#define SMEM_U32 (BATCH * DPITCH)          // 8320 >= 2*BUFLEN (2880)

__device__ double       g_partials[NBLOCKS];
__device__ unsigned int g_done = 0;
// packed, tf32-converted, zero-padded scratch (static device arrays: legal)
__device__ __align__(16) uint32_t g_img_packed[CCH * XPAD * XPAD];          // 3.55 MB
__device__ __align__(16) uint32_t g_psf_packed[CCH * KSZ * BATCH * KSZ];    // 393 KB

static __device__ __forceinline__ uint32_t f2tf(float v) {
    uint32_t r;
    asm("cvt.rna.tf32.f32 %0, %1;" : "=r"(r) : "f"(v));
    return r;
}
static __device__ __forceinline__ uint32_t smem_u32(const void* p) {
    uint32_t a;
    asm("{ .reg .u64 t; cvta.to.shared.u64 t, %1; cvt.u32.u64 %0, t; }"
        : "=r"(a) : "l"(p));
    return a;
}
static __device__ __forceinline__ void cp_async16(uint32_t dst, const void* src) {
    asm volatile("cp.async.cg.shared.global [%0], [%1], 16;"
                 :: "r"(dst), "l"(src) : "memory");
}

// D(16x8,f32) += A(16x8,tf32,row) * B(8x8,tf32,col)
static __device__ __forceinline__ void mma_tf32(float* d,
                                                uint32_t a0, uint32_t a1,
                                                uint32_t a2, uint32_t a3,
                                                uint32_t b0, uint32_t b1) {
    asm volatile(
        "mma.sync.aligned.m16n8k8.row.col.f32.tf32.tf32.f32 "
        "{%0,%1,%2,%3}, {%4,%5,%6,%7}, {%8,%9}, {%0,%1,%2,%3};"
        : "+f"(d[0]), "+f"(d[1]), "+f"(d[2]), "+f"(d[3])
        : "r"(a0), "r"(a1), "r"(a2), "r"(a3), "r"(b0), "r"(b1));
}

// ---------------- pack pre-pass ----------------
__global__ void pack_kernel(const float* __restrict__ img,
                            const float* __restrict__ psf) {
    const int stride = gridDim.x * blockDim.x;
    const int n_img = CCH * XPAD * XPAD;
    for (int i = blockIdx.x * blockDim.x + threadIdx.x; i < n_img; i += stride) {
        int c   = i / (XPAD * XPAD);
        int rem = i - c * XPAD * XPAD;
        int X = rem / XPAD, Y = rem - (rem / XPAD) * XPAD;
        int gx = X - PAD_LO, gy = Y - PAD_LO;
        uint32_t v = 0u;
        if ((unsigned)gx < W_IMG && (unsigned)gy < H_IMG)
            v = f2tf(img[((size_t)gx * H_IMG + gy) * CCH + c]);
        g_img_packed[i] = v;
    }
    const int n_psf = CCH * KSZ * BATCH * KSZ;
    for (int i = blockIdx.x * blockDim.x + threadIdx.x; i < n_psf; i += stride) {
        int c    = i / (KSZ * BATCH * KSZ);
        int rem  = i - c * (KSZ * BATCH * KSZ);
        int r    = rem / (BATCH * KSZ);
        int rem2 = rem - r * (BATCH * KSZ);
        int b = rem2 >> 5, s = rem2 & 31;
        g_psf_packed[i] = f2tf(psf[((size_t)(b * KSZ + r) * KSZ + s) * CCH + c]);
    }
}

// ---------------- main kernel ----------------
__global__ __launch_bounds__(NTH, 3)
void conv_mma_kernel(const float* __restrict__ obs,
                     float* __restrict__ out,
                     long long loss_idx)
{
    __shared__ __align__(16) uint32_t s_u[SMEM_U32];
    __shared__ float  s_red[NTH / 32];
    __shared__ double s_dred[NTH / 32];
    __shared__ int    s_last;

    const int tid   = threadIdx.x;
    const int wid   = tid >> 5;
    const int lane  = tid & 31;
    const int yh    = blockIdx.x;        // which 256-row block
    const int x     = blockIdx.y;
    const int c     = blockIdx.z;
    const int ybase = yh * MCTA;

    const int seg = wid >> 2;            // warpgroup 0/1 -> segment
    const int wl  = wid & 3;             // warp within group
    const int g   = lane >> 2;           // fragment row
    const int t4  = lane & 3;            // fragment col/k

    float d[2][4][4];
#pragma unroll
    for (int mt = 0; mt < 2; ++mt)
#pragma unroll
        for (int nt = 0; nt < 4; ++nt)
#pragma unroll
            for (int i = 0; i < 4; ++i) d[mt][nt][i] = 0.f;

    const uint32_t su = smem_u32(s_u);

    // async stage of PSF row r into buffer p (tf32 bits, halo pre-baked)
    auto stage_async = [&](int r, int p) {
        // raw image row: 288 contiguous tf32 words for this CTA's 256 rows + halo
        const uint32_t* src_raw =
            g_img_packed + ((size_t)(c * XPAD + (x + r))) * XPAD + ybase;
        if (tid < RAWLEN / 4)
            cp_async16(su + (uint32_t)(RAW_OFF(p) + tid * 4) * 4,
                       src_raw + tid * 4);
        // B tile: 4KB contiguous -> rows of pitch 36 (one 16B chunk per thread)
        const uint32_t* src_b =
            g_psf_packed + ((size_t)(c * KSZ + r) * BATCH) * KSZ;
        {
            int b = tid >> 3, s4 = tid & 7;
            cp_async16(su + (uint32_t)(B_OFF(p) + b * BPITCH + s4 * 4) * 4,
                       src_b + b * KSZ + s4 * 4);
        }
        asm volatile("cp.async.commit_group;" ::: "memory");
    };

    stage_async(0, 0);
    asm volatile("cp.async.wait_group 0;" ::: "memory");
    __syncthreads();

    const int abase = seg * MSEG + 32 * wl + g + t4;

#pragma unroll 1
    for (int r = 0; r < KSZ; ++r) {
        if (r + 1 < KSZ) stage_async(r + 1, (r + 1) & 1);

        const uint32_t* raw = s_u + RAW_OFF(r & 1);
        const uint32_t* Bs  = s_u + B_OFF(r & 1);

        // Toeplitz A register cache: 14 distinct words cover all fragments
        uint32_t rv[14];
#pragma unroll
        for (int t = 0; t < 14; ++t) rv[t] = raw[abase + 4 * t];

#pragma unroll
        for (int k8 = 0; k8 < 4; ++k8) {
            uint32_t b0[4], b1[4];
#pragma unroll
            for (int nt = 0; nt < 4; ++nt) {
                const int off = (nt * 8 + g) * BPITCH + k8 * 8 + t4;
                b0[nt] = Bs[off];
                b1[nt] = Bs[off + 4];
            }
#pragma unroll
            for (int mt = 0; mt < 2; ++mt) {
                const int t0 = 4 * mt + 2 * k8;
                const uint32_t a0 = rv[t0];
                const uint32_t a1 = rv[t0 + 2];
                const uint32_t a2 = rv[t0 + 1];
                const uint32_t a3 = rv[t0 + 3];
#pragma unroll
                for (int nt = 0; nt < 4; ++nt)
                    mma_tf32(d[mt][nt], a0, a1, a2, a3, b0[nt], b1[nt]);
            }
        }

        asm volatile("cp.async.wait_group 0;" ::: "memory");
        __syncthreads();
    }

    // ---------------- epilogue: D -> smem transpose (256 rows) -> gmem + loss ----------------
#pragma unroll
    for (int mt = 0; mt < 2; ++mt)
#pragma unroll
        for (int nt = 0; nt < 4; ++nt)
#pragma unroll
            for (int i = 0; i < 4; ++i) {
                const int n = nt * 8 + 2 * t4 + (i & 1);
                const int y = seg * MSEG + 32 * wl + 16 * mt + g + ((i >> 1) ? 8 : 0);
                s_u[n * DPITCH + y] = __float_as_uint(d[mt][nt][i]);
            }
    __syncthreads();

    // thread -> (batch b = tid/8, y-eighth q = tid%8), 32 consecutive y each
    const int bb = tid >> 3;
    const int yq = tid & 7;
    const uint32_t* drow = s_u + bb * DPITCH + yq * 32;
    const size_t obase =
        ((size_t)((size_t)bb * W_IMG + x) * H_IMG + (ybase + yq * 32)) * CCH + c;
    float lsum = 0.f;
#pragma unroll
    for (int i = 0; i < 32; ++i) {
        float p = __uint_as_float(drow[i]);
        size_t idx = obase + (size_t)i * CCH;
        out[idx] = p;
        float dd = obs[idx] - p;
        lsum += dd * dd;
    }

    // block reduce loss (8 warps)
#pragma unroll
    for (int off = 16; off; off >>= 1)
        lsum += __shfl_xor_sync(0xffffffffu, lsum, off);
    if (lane == 0) s_red[wid] = lsum;
    __syncthreads();

    const int lin = yh + YH * (x + W_IMG * c);
    if (tid == 0) {
        float bsum = 0.f;
#pragma unroll
        for (int w = 0; w < NTH / 32; ++w) bsum += s_red[w];
        g_partials[lin] = (double)bsum;
        __threadfence();
        unsigned prev = atomicAdd(&g_done, 1u);
        s_last = (prev == NBLOCKS - 1);
    }
    __syncthreads();

    if (s_last) {
        double dsum = 0.0;
        for (int i = tid; i < NBLOCKS; i += NTH) dsum += g_partials[i];
#pragma unroll
        for (int off = 16; off; off >>= 1)
            dsum += __shfl_xor_sync(0xffffffffu, dsum, off);
        if (lane == 0) s_dred[wid] = dsum;
        __syncthreads();
        if (tid == 0) {
            double tot = 0.0;
#pragma unroll
            for (int w = 0; w < NTH / 32; ++w) tot += s_dred[w];
            out[loss_idx] = (float)(tot / (double)N_PRED);
            g_done = 0;   // self-reset: deterministic across graph replays
        }
    }
}

extern "C" void kernel_launch(void* const* d_in, const int* in_sizes, int n_in,
                              void* d_out, int out_size) {
    const float* obs = nullptr;
    const float* img = nullptr;
    const float* psf = nullptr;
    for (int i = 0; i < n_in; ++i) {
        long long n = in_sizes[i];
        if (n == (long long)BATCH * W_IMG * H_IMG * CCH)      obs = (const float*)d_in[i];
        else if (n == (long long)W_IMG * H_IMG * CCH)         img = (const float*)d_in[i];
        else if (n == (long long)BATCH * KSZ * KSZ * CCH)     psf = (const float*)d_in[i];
    }
    float* out = (float*)d_out;

    pack_kernel<<<1024, 256>>>(img, psf);
    dim3 grid(YH, W_IMG, CCH);   // 3072 CTAs
    conv_mma_kernel<<<grid, NTH>>>(obs, out, (long long)out_size - 1);
}

// round 16
// speedup vs baseline: 1.4923x; 1.1174x over previous
#include <cuda_runtime.h>
#include <cstdint>

// ---------------- problem constants ----------------
#define W_IMG 512
#define H_IMG 512
#define CCH   3
#define BATCH 32
#define KSZ   32
#define PAD_LO 15            // SAME padding, even kernel: lo=15, hi=16
#define XPAD  544            // 15 + 512 + 17 (halo baked into packed image)

#define MTILE 128            // y-pixels per CTA (GEMM M)
#define NTH   128            // 4 warps
#define YTILES (H_IMG / MTILE)                // 4
#define NBLOCKS (YTILES * W_IMG * CCH)        // 6144
#define N_PRED ((size_t)BATCH * W_IMG * H_IMG * CCH)

// smem union (u32 units):
//   3 staging bufs p: raw[160] tf32 @ RAW_OFF(p),
//                     B tf32 n-major [32 b rows x pitch 36] @ B_OFF(p)
//   epilogue:         s_d [32 n x pitch 132] floats, reuses same storage
#define RAWLEN 160
#define BPITCH 36            // pitch ≡ 4 (mod 32): conflict-free frag loads
#define BUFLEN (RAWLEN + BATCH * BPITCH)   // 1312
#define RAW_OFF(p) ((p) * BUFLEN)
#define B_OFF(p)   ((p) * BUFLEN + RAWLEN)
#define DPITCH 132
#define SMEM_U32 (BATCH * DPITCH)          // 4224 >= 3*BUFLEN (3936)

__device__ double       g_partials[NBLOCKS];
__device__ unsigned int g_done = 0;
// packed, tf32-converted, zero-padded scratch (static device arrays: legal)
__device__ __align__(16) uint32_t g_img_packed[CCH * XPAD * XPAD];          // 3.55 MB
__device__ __align__(16) uint32_t g_psf_packed[CCH * KSZ * BATCH * KSZ];    // 393 KB

static __device__ __forceinline__ uint32_t f2tf(float v) {
    uint32_t r;
    asm("cvt.rna.tf32.f32 %0, %1;" : "=r"(r) : "f"(v));
    return r;
}
static __device__ __forceinline__ uint32_t smem_u32(const void* p) {
    uint32_t a;
    asm("{ .reg .u64 t; cvta.to.shared.u64 t, %1; cvt.u32.u64 %0, t; }"
        : "=r"(a) : "l"(p));
    return a;
}
static __device__ __forceinline__ void cp_async16(uint32_t dst, const void* src) {
    asm volatile("cp.async.cg.shared.global [%0], [%1], 16;"
                 :: "r"(dst), "l"(src) : "memory");
}

// D(16x8,f32) += A(16x8,tf32,row) * B(8x8,tf32,col)
static __device__ __forceinline__ void mma_tf32(float* d,
                                                uint32_t a0, uint32_t a1,
                                                uint32_t a2, uint32_t a3,
                                                uint32_t b0, uint32_t b1) {
    asm volatile(
        "mma.sync.aligned.m16n8k8.row.col.f32.tf32.tf32.f32 "
        "{%0,%1,%2,%3}, {%4,%5,%6,%7}, {%8,%9}, {%0,%1,%2,%3};"
        : "+f"(d[0]), "+f"(d[1]), "+f"(d[2]), "+f"(d[3])
        : "r"(a0), "r"(a1), "r"(a2), "r"(a3), "r"(b0), "r"(b1));
}

// ---------------- pack pre-pass ----------------
__global__ void pack_kernel(const float* __restrict__ img,
                            const float* __restrict__ psf) {
    const int stride = gridDim.x * blockDim.x;
    const int n_img = CCH * XPAD * XPAD;
    for (int i = blockIdx.x * blockDim.x + threadIdx.x; i < n_img; i += stride) {
        int c   = i / (XPAD * XPAD);
        int rem = i - c * XPAD * XPAD;
        int X = rem / XPAD, Y = rem - (rem / XPAD) * XPAD;
        int gx = X - PAD_LO, gy = Y - PAD_LO;
        uint32_t v = 0u;
        if ((unsigned)gx < W_IMG && (unsigned)gy < H_IMG)
            v = f2tf(img[((size_t)gx * H_IMG + gy) * CCH + c]);
        g_img_packed[i] = v;
    }
    const int n_psf = CCH * KSZ * BATCH * KSZ;
    for (int i = blockIdx.x * blockDim.x + threadIdx.x; i < n_psf; i += stride) {
        int c    = i / (KSZ * BATCH * KSZ);
        int rem  = i - c * (KSZ * BATCH * KSZ);
        int r    = rem / (BATCH * KSZ);
        int rem2 = rem - r * (BATCH * KSZ);
        int b = rem2 >> 5, s = rem2 & 31;
        g_psf_packed[i] = f2tf(psf[((size_t)(b * KSZ + r) * KSZ + s) * CCH + c]);
    }
}

// ---------------- main kernel ----------------
__global__ __launch_bounds__(NTH, 6)
void conv_mma_kernel(const float* __restrict__ obs,
                     float* __restrict__ out,
                     long long loss_idx)
{
    __shared__ __align__(16) uint32_t s_u[SMEM_U32];
    __shared__ float  s_red[NTH / 32];
    __shared__ double s_dred[NTH / 32];
    __shared__ int    s_last;

    const int tid   = threadIdx.x;
    const int wid   = tid >> 5;
    const int lane  = tid & 31;
    const int ytile = blockIdx.x;
    const int x     = blockIdx.y;
    const int c     = blockIdx.z;
    const int y0    = ytile * MTILE;

    const int g  = lane >> 2;        // fragment row
    const int t4 = lane & 3;         // fragment col/k

    float d[2][4][4];
#pragma unroll
    for (int mt = 0; mt < 2; ++mt)
#pragma unroll
        for (int nt = 0; nt < 4; ++nt)
#pragma unroll
            for (int i = 0; i < 4; ++i) d[mt][nt][i] = 0.f;

    const uint32_t su = smem_u32(s_u);

    // async stage of PSF row r into buffer p (tf32 bits, halo pre-baked)
    auto stage_async = [&](int r, int p) {
        const uint32_t* src_raw =
            g_img_packed + ((size_t)(c * XPAD + (x + r))) * XPAD + y0;
        if (tid < RAWLEN / 4)
            cp_async16(su + (uint32_t)(RAW_OFF(p) + tid * 4) * 4,
                       src_raw + tid * 4);
        const uint32_t* src_b =
            g_psf_packed + ((size_t)(c * KSZ + r) * BATCH) * KSZ;
#pragma unroll
        for (int j = 0; j < 2; ++j) {
            int e = tid + j * NTH;          // 16B-chunk id: b = e/8, s4 = e%8
            int b = e >> 3, s4 = e & 7;
            cp_async16(su + (uint32_t)(B_OFF(p) + b * BPITCH + s4 * 4) * 4,
                       src_b + b * KSZ + s4 * 4);
        }
        asm volatile("cp.async.commit_group;" ::: "memory");
    };

    // prologue: stage rows 0 and 1, wait only for row 0
    stage_async(0, 0);
    stage_async(1, 1);
    asm volatile("cp.async.wait_group 1;" ::: "memory");
    __syncthreads();

    const int abase = 32 * wid + g + t4;

    int pr = 0;       // read buffer for iter r
    int pw = 2;       // write buffer for iter r's prefetch (row r+2)

#pragma unroll 1
    for (int r = 0; r < KSZ; ++r) {
        if (r + 2 < KSZ) stage_async(r + 2, pw);   // prefetch distance 2

        const uint32_t* raw = s_u + RAW_OFF(pr);
        const uint32_t* Bs  = s_u + B_OFF(pr);

        // Toeplitz A register cache: 14 distinct words cover all fragments
        uint32_t rv[14];
#pragma unroll
        for (int t = 0; t < 14; ++t) rv[t] = raw[abase + 4 * t];

#pragma unroll
        for (int k8 = 0; k8 < 4; ++k8) {
            uint32_t b0[4], b1[4];
#pragma unroll
            for (int nt = 0; nt < 4; ++nt) {
                const int off = (nt * 8 + g) * BPITCH + k8 * 8 + t4;
                b0[nt] = Bs[off];
                b1[nt] = Bs[off + 4];
            }
#pragma unroll
            for (int mt = 0; mt < 2; ++mt) {
                const int t0 = 4 * mt + 2 * k8;
                const uint32_t a0 = rv[t0];
                const uint32_t a1 = rv[t0 + 2];
                const uint32_t a2 = rv[t0 + 1];
                const uint32_t a3 = rv[t0 + 3];
#pragma unroll
                for (int nt = 0; nt < 4; ++nt)
                    mma_tf32(d[mt][nt], a0, a1, a2, a3, b0[nt], b1[nt]);
            }
        }

        // require only row r+1 complete; leave row r+2's group in flight
        if (r + 2 < KSZ)
            asm volatile("cp.async.wait_group 1;" ::: "memory");
        else
            asm volatile("cp.async.wait_group 0;" ::: "memory");
        __syncthreads();

        pr = (pr == 2) ? 0 : pr + 1;
        pw = (pw == 2) ? 0 : pw + 1;
    }

    // ---------------- epilogue: D -> smem transpose -> gmem + loss ----------------
#pragma unroll
    for (int mt = 0; mt < 2; ++mt)
#pragma unroll
        for (int nt = 0; nt < 4; ++nt)
#pragma unroll
            for (int i = 0; i < 4; ++i) {
                const int n = nt * 8 + 2 * t4 + (i & 1);
                const int y = 32 * wid + 16 * mt + g + ((i >> 1) ? 8 : 0);
                s_u[n * DPITCH + y] = __float_as_uint(d[mt][nt][i]);
            }
    __syncthreads();

    const int bb = tid >> 2;
    const int yq = tid & 3;
    const uint32_t* drow = s_u + bb * DPITCH + yq * 32;
    const size_t obase =
        ((size_t)((size_t)bb * W_IMG + x) * H_IMG + (y0 + yq * 32)) * CCH + c;
    float lsum = 0.f;
#pragma unroll
    for (int i = 0; i < 32; ++i) {
        float p = __uint_as_float(drow[i]);
        size_t idx = obase + (size_t)i * CCH;
        out[idx] = p;
        float dd = obs[idx] - p;
        lsum += dd * dd;
    }

#pragma unroll
    for (int off = 16; off; off >>= 1)
        lsum += __shfl_xor_sync(0xffffffffu, lsum, off);
    if (lane == 0) s_red[wid] = lsum;
    __syncthreads();

    const int lin = ytile + YTILES * (x + W_IMG * c);
    if (tid == 0) {
        float bsum = 0.f;
#pragma unroll
        for (int w = 0; w < NTH / 32; ++w) bsum += s_red[w];
        g_partials[lin] = (double)bsum;
        __threadfence();
        unsigned prev = atomicAdd(&g_done, 1u);
        s_last = (prev == NBLOCKS - 1);
    }
    __syncthreads();

    if (s_last) {
        double dsum = 0.0;
        for (int i = tid; i < NBLOCKS; i += NTH) dsum += g_partials[i];
#pragma unroll
        for (int off = 16; off; off >>= 1)
            dsum += __shfl_xor_sync(0xffffffffu, dsum, off);
        if (lane == 0) s_dred[wid] = dsum;
        __syncthreads();
        if (tid == 0) {
            double tot = 0.0;
#pragma unroll
            for (int w = 0; w < NTH / 32; ++w) tot += s_dred[w];
            out[loss_idx] = (float)(tot / (double)N_PRED);
            g_done = 0;   // self-reset: deterministic across graph replays
        }
    }
}

extern "C" void kernel_launch(void* const* d_in, const int* in_sizes, int n_in,
                              void* d_out, int out_size) {
    const float* obs = nullptr;
    const float* img = nullptr;
    const float* psf = nullptr;
    for (int i = 0; i < n_in; ++i) {
        long long n = in_sizes[i];
        if (n == (long long)BATCH * W_IMG * H_IMG * CCH)      obs = (const float*)d_in[i];
        else if (n == (long long)W_IMG * H_IMG * CCH)         img = (const float*)d_in[i];
        else if (n == (long long)BATCH * KSZ * KSZ * CCH)     psf = (const float*)d_in[i];
    }
    float* out = (float*)d_out;

    pack_kernel<<<1024, 256>>>(img, psf);
    dim3 grid(YTILES, W_IMG, CCH);   // 6144 CTAs
    conv_mma_kernel<<<grid, NTH>>>(obs, out, (long long)out_size - 1);
}

// round 17
// speedup vs baseline: 1.5665x; 1.0497x over previous
#include <cuda_runtime.h>
#include <cstdint>

// ---------------- problem constants ----------------
#define W_IMG 512
#define H_IMG 512
#define CCH   3
#define BATCH 32
#define KSZ   32
#define PAD_LO 15            // SAME padding, even kernel: lo=15, hi=16
#define XPAD  544            // 15 + 512 + 17 (halo baked into packed image)

#define MTILE 128            // y-pixels per CTA (GEMM M)
#define NTH   128            // 4 warps
#define YTILES (H_IMG / MTILE)                // 4
#define NBLOCKS (YTILES * W_IMG * CCH)        // 6144
#define N_PRED ((size_t)BATCH * W_IMG * H_IMG * CCH)

// smem union (u32 units): 2 superstep buffers, each covering 2 PSF rows:
//   raw0[160], raw1[160], B0[1024], B1[1024]  (B in fragment-major order)
//   epilogue: s_d [32 n x pitch 132] floats, reuses same storage
#define RAWLEN 160
#define BWORDS 1024          // one (c,r) B tile: [k8][n][t4*2+h], contiguous
#define BUFLEN (2 * RAWLEN + 2 * BWORDS)   // 2368
#define RAW_OFF(p, rr) ((p) * BUFLEN + (rr) * RAWLEN)
#define B_OFF(p, rr)   ((p) * BUFLEN + 2 * RAWLEN + (rr) * BWORDS)
#define DPITCH 132
#define SMEM_U32 (2 * BUFLEN)              // 4736 >= epilogue 4224

__device__ double       g_partials[NBLOCKS];
__device__ unsigned int g_done = 0;
// packed, tf32-converted scratch (static device arrays: legal)
__device__ __align__(16) uint32_t g_img_packed[CCH * XPAD * XPAD];          // 3.55 MB
__device__ __align__(16) uint32_t g_psf_packed[CCH * KSZ * BWORDS];         // 393 KB

static __device__ __forceinline__ uint32_t f2tf(float v) {
    uint32_t r;
    asm("cvt.rna.tf32.f32 %0, %1;" : "=r"(r) : "f"(v));
    return r;
}
static __device__ __forceinline__ uint32_t smem_u32(const void* p) {
    uint32_t a;
    asm("{ .reg .u64 t; cvta.to.shared.u64 t, %1; cvt.u32.u64 %0, t; }"
        : "=r"(a) : "l"(p));
    return a;
}
static __device__ __forceinline__ void cp_async16(uint32_t dst, const void* src) {
    asm volatile("cp.async.cg.shared.global [%0], [%1], 16;"
                 :: "r"(dst), "l"(src) : "memory");
}

// D(16x8,f32) += A(16x8,tf32,row) * B(8x8,tf32,col)
static __device__ __forceinline__ void mma_tf32(float* d,
                                                uint32_t a0, uint32_t a1,
                                                uint32_t a2, uint32_t a3,
                                                uint32_t b0, uint32_t b1) {
    asm volatile(
        "mma.sync.aligned.m16n8k8.row.col.f32.tf32.tf32.f32 "
        "{%0,%1,%2,%3}, {%4,%5,%6,%7}, {%8,%9}, {%0,%1,%2,%3};"
        : "+f"(d[0]), "+f"(d[1]), "+f"(d[2]), "+f"(d[3])
        : "r"(a0), "r"(a1), "r"(a2), "r"(a3), "r"(b0), "r"(b1));
}

// ---------------- pack pre-pass ----------------
__global__ void pack_kernel(const float* __restrict__ img,
                            const float* __restrict__ psf) {
    const int stride = gridDim.x * blockDim.x;
    const int n_img = CCH * XPAD * XPAD;
    for (int i = blockIdx.x * blockDim.x + threadIdx.x; i < n_img; i += stride) {
        int c   = i / (XPAD * XPAD);
        int rem = i - c * XPAD * XPAD;
        int X = rem / XPAD, Y = rem - (rem / XPAD) * XPAD;
        int gx = X - PAD_LO, gy = Y - PAD_LO;
        uint32_t v = 0u;
        if ((unsigned)gx < W_IMG && (unsigned)gy < H_IMG)
            v = f2tf(img[((size_t)gx * H_IMG + gy) * CCH + c]);
        g_img_packed[i] = v;
    }
    // PSF fragment-major: word = ((c*KSZ + r)*4 + k8)*256 + n*8 + t4*2 + h,
    // holding psf value at k = k8*8 + t4 + 4*h, batch n, row r, channel c.
    const int n_psf = CCH * KSZ * BWORDS;
    for (int i = blockIdx.x * blockDim.x + threadIdx.x; i < n_psf; i += stride) {
        int cr  = i / BWORDS;            // c*KSZ + r
        int w   = i - cr * BWORDS;
        int c   = cr / KSZ;
        int r   = cr - c * KSZ;
        int k8  = w >> 8;
        int q   = w & 255;
        int n   = q >> 3;
        int t4  = (q >> 1) & 3;
        int h   = q & 1;
        int k   = k8 * 8 + t4 + 4 * h;
        g_psf_packed[i] = f2tf(psf[((size_t)(n * KSZ + r) * KSZ + k) * CCH + c]);
    }
}

// ---------------- main kernel ----------------
__global__ __launch_bounds__(NTH, 6)
void conv_mma_kernel(const float* __restrict__ obs,
                     float* __restrict__ out,
                     long long loss_idx)
{
    __shared__ __align__(16) uint32_t s_u[SMEM_U32];
    __shared__ float  s_red[NTH / 32];
    __shared__ double s_dred[NTH / 32];
    __shared__ int    s_last;

    const int tid   = threadIdx.x;
    const int wid   = tid >> 5;
    const int lane  = tid & 31;
    const int ytile = blockIdx.x;
    const int x     = blockIdx.y;
    const int c     = blockIdx.z;
    const int y0    = ytile * MTILE;

    const int g  = lane >> 2;        // fragment row
    const int t4 = lane & 3;         // fragment col/k

    float d[2][4][4];
#pragma unroll
    for (int mt = 0; mt < 2; ++mt)
#pragma unroll
        for (int nt = 0; nt < 4; ++nt)
#pragma unroll
            for (int i = 0; i < 4; ++i) d[mt][nt][i] = 0.f;

    const uint32_t su = smem_u32(s_u);

    // async stage of superstep s (PSF rows 2s, 2s+1) into buffer p
    auto stage_async = [&](int s, int p) {
        const int r0 = 2 * s;
#pragma unroll
        for (int rr = 0; rr < 2; ++rr) {
            const uint32_t* src_raw =
                g_img_packed + ((size_t)(c * XPAD + (x + r0 + rr))) * XPAD + y0;
            if (tid < RAWLEN / 4)
                cp_async16(su + (uint32_t)(RAW_OFF(p, rr) + tid * 4) * 4,
                           src_raw + tid * 4);
            // B tile: 4KB contiguous in fragment-major order (coalesced)
            const uint32_t* src_b =
                g_psf_packed + ((size_t)(c * KSZ + r0 + rr)) * BWORDS;
#pragma unroll
            for (int j = 0; j < 2; ++j) {
                int e = tid + j * NTH;   // 16B chunk id, 256 chunks
                cp_async16(su + (uint32_t)(B_OFF(p, rr) + e * 4) * 4,
                           src_b + e * 4);
            }
        }
        asm volatile("cp.async.commit_group;" ::: "memory");
    };

    stage_async(0, 0);
    asm volatile("cp.async.wait_group 0;" ::: "memory");
    __syncthreads();

    const int abase = 32 * wid + g + t4;
    const int bfrag = g * 4 + t4;    // uint2 offset within a k8 block (n=g part)

#pragma unroll 1
    for (int s = 0; s < KSZ / 2; ++s) {
        const int p = s & 1;
        if (s + 1 < KSZ / 2) stage_async(s + 1, p ^ 1);

#pragma unroll
        for (int rr = 0; rr < 2; ++rr) {
            const uint32_t* raw = s_u + RAW_OFF(p, rr);
            const uint2*    Bs2 = reinterpret_cast<const uint2*>(s_u + B_OFF(p, rr));

            // Toeplitz A register cache: 14 distinct words cover all fragments
            uint32_t rv[14];
#pragma unroll
            for (int t = 0; t < 14; ++t) rv[t] = raw[abase + 4 * t];

#pragma unroll
            for (int k8 = 0; k8 < 4; ++k8) {
                uint32_t b0[4], b1[4];
#pragma unroll
                for (int nt = 0; nt < 4; ++nt) {
                    // uint2 index: k8*128 + (nt*8+g)*4 + t4 — all-distinct banks
                    uint2 v = Bs2[k8 * 128 + nt * 32 + bfrag];
                    b0[nt] = v.x;            // k = k8*8 + t4
                    b1[nt] = v.y;            // k = k8*8 + t4 + 4
                }
#pragma unroll
                for (int mt = 0; mt < 2; ++mt) {
                    const int t0 = 4 * mt + 2 * k8;
                    const uint32_t a0 = rv[t0];
                    const uint32_t a1 = rv[t0 + 2];
                    const uint32_t a2 = rv[t0 + 1];
                    const uint32_t a3 = rv[t0 + 3];
#pragma unroll
                    for (int nt = 0; nt < 4; ++nt)
                        mma_tf32(d[mt][nt], a0, a1, a2, a3, b0[nt], b1[nt]);
                }
            }
        }

        asm volatile("cp.async.wait_group 0;" ::: "memory");
        __syncthreads();
    }

    // ---------------- epilogue: D -> smem transpose -> gmem + loss ----------------
#pragma unroll
    for (int mt = 0; mt < 2; ++mt)
#pragma unroll
        for (int nt = 0; nt < 4; ++nt)
#pragma unroll
            for (int i = 0; i < 4; ++i) {
                const int n = nt * 8 + 2 * t4 + (i & 1);
                const int y = 32 * wid + 16 * mt + g + ((i >> 1) ? 8 : 0);
                s_u[n * DPITCH + y] = __float_as_uint(d[mt][nt][i]);
            }
    __syncthreads();

    const int bb = tid >> 2;
    const int yq = tid & 3;
    const uint32_t* drow = s_u + bb * DPITCH + yq * 32;
    const size_t obase =
        ((size_t)((size_t)bb * W_IMG + x) * H_IMG + (y0 + yq * 32)) * CCH + c;
    float lsum = 0.f;
#pragma unroll
    for (int i = 0; i < 32; ++i) {
        float p = __uint_as_float(drow[i]);
        size_t idx = obase + (size_t)i * CCH;
        out[idx] = p;
        float dd = obs[idx] - p;
        lsum += dd * dd;
    }

#pragma unroll
    for (int off = 16; off; off >>= 1)
        lsum += __shfl_xor_sync(0xffffffffu, lsum, off);
    if (lane == 0) s_red[wid] = lsum;
    __syncthreads();

    const int lin = ytile + YTILES * (x + W_IMG * c);
    if (tid == 0) {
        float bsum = 0.f;
#pragma unroll
        for (int w = 0; w < NTH / 32; ++w) bsum += s_red[w];
        g_partials[lin] = (double)bsum;
        __threadfence();
        unsigned prev = atomicAdd(&g_done, 1u);
        s_last = (prev == NBLOCKS - 1);
    }
    __syncthreads();

    if (s_last) {
        double dsum = 0.0;
        for (int i = tid; i < NBLOCKS; i += NTH) dsum += g_partials[i];
#pragma unroll
        for (int off = 16; off; off >>= 1)
            dsum += __shfl_xor_sync(0xffffffffu, dsum, off);
        if (lane == 0) s_dred[wid] = dsum;
        __syncthreads();
        if (tid == 0) {
            double tot = 0.0;
#pragma unroll
            for (int w = 0; w < NTH / 32; ++w) tot += s_dred[w];
            out[loss_idx] = (float)(tot / (double)N_PRED);
            g_done = 0;   // self-reset: deterministic across graph replays
        }
    }
}

extern "C" void kernel_launch(void* const* d_in, const int* in_sizes, int n_in,
                              void* d_out, int out_size) {
    const float* obs = nullptr;
    const float* img = nullptr;
    const float* psf = nullptr;
    for (int i = 0; i < n_in; ++i) {
        long long n = in_sizes[i];
        if (n == (long long)BATCH * W_IMG * H_IMG * CCH)      obs = (const float*)d_in[i];
        else if (n == (long long)W_IMG * H_IMG * CCH)         img = (const float*)d_in[i];
        else if (n == (long long)BATCH * KSZ * KSZ * CCH)     psf = (const float*)d_in[i];
    }
    float* out = (float*)d_out;

    pack_kernel<<<1024, 256>>>(img, psf);
    dim3 grid(YTILES, W_IMG, CCH);   // 6144 CTAs
    conv_mma_kernel<<<grid, NTH>>>(obs, out, (long long)out_size - 1);
}